// round 1
// baseline (speedup 1.0000x reference)
#include <cuda_runtime.h>

#define NN 20000
#define EE 300000
#define HH 128
#define LL 8

// Scratch (device globals: allocation-free contract)
__device__ __align__(16) float g_x  [NN * HH];   // node features
__device__ __align__(16) float g_e  [EE * HH];   // edge features (updated in place)
__device__ __align__(16) float g_xs [NN * HH];   // x @ W_src (per layer)
__device__ __align__(16) float g_xd [NN * HH];   // x @ W_dst (per layer)
__device__ __align__(16) float g_agg[NN * HH];   // scatter-add accumulator

// ----------------------------------------------------------------------------
// Shared GEMM microkernel: acc[8][4] += A_tile[64,128] @ W[128,128]
// Thread layout (256 thr): lane = tid&31 -> cols j0 = lane*4 (4 cols),
//                          wrow = tid>>5 -> rows r0 = wrow*8 (8 rows).
// A reads are warp-broadcast LDS.128; W reads are coalesced 512B LDG.128.
// ----------------------------------------------------------------------------
__device__ __forceinline__ void gemm128_accum(const float* __restrict__ As,
                                              const float* __restrict__ W,
                                              int r0, int j0, float acc[8][4]) {
#pragma unroll 2
    for (int k4 = 0; k4 < 32; k4++) {
        const float* wr = W + (k4 * 4) * HH + j0;
        float4 w0 = *(const float4*)(wr);
        float4 w1 = *(const float4*)(wr + HH);
        float4 w2 = *(const float4*)(wr + 2 * HH);
        float4 w3 = *(const float4*)(wr + 3 * HH);
#pragma unroll
        for (int r = 0; r < 8; r++) {
            float4 a = *(const float4*)(As + (r0 + r) * HH + k4 * 4);
            acc[r][0] += a.x * w0.x + a.y * w1.x + a.z * w2.x + a.w * w3.x;
            acc[r][1] += a.x * w0.y + a.y * w1.y + a.z * w2.y + a.w * w3.y;
            acc[r][2] += a.x * w0.z + a.y * w1.z + a.z * w2.z + a.w * w3.z;
            acc[r][3] += a.x * w0.w + a.y * w1.w + a.z * w2.w + a.w * w3.w;
        }
    }
}

__device__ __forceinline__ void init_acc(float acc[8][4], float4 b) {
#pragma unroll
    for (int r = 0; r < 8; r++) {
        acc[r][0] = b.x; acc[r][1] = b.y; acc[r][2] = b.z; acc[r][3] = b.w;
    }
}

__device__ __forceinline__ void relu_to_smem(float* As, int r0, int j0, float acc[8][4]) {
#pragma unroll
    for (int r = 0; r < 8; r++) {
        float4 h = make_float4(fmaxf(acc[r][0], 0.f), fmaxf(acc[r][1], 0.f),
                               fmaxf(acc[r][2], 0.f), fmaxf(acc[r][3], 0.f));
        *(float4*)(As + (r0 + r) * HH + j0) = h;
    }
}

// ----------------------------------------------------------------------------
// Zero the scatter accumulator
// ----------------------------------------------------------------------------
__global__ void zero_agg_kernel() {
    int i = blockIdx.x * blockDim.x + threadIdx.x;   // NN*HH/4 = 640000 float4
    ((float4*)g_agg)[i] = make_float4(0.f, 0.f, 0.f, 0.f);
}

// ----------------------------------------------------------------------------
// Encoders: MLP2 with tiny input dim K1 (6 for nodes, 3 for edges)
// DST: 0 -> g_x, 1 -> g_e
// ----------------------------------------------------------------------------
template <int K1, int DST>
__global__ __launch_bounds__(256) void encoder_kernel(
    const float* __restrict__ in, const float* __restrict__ w1,
    const float* __restrict__ b1, const float* __restrict__ w2,
    const float* __restrict__ b2, int rows) {
    __shared__ __align__(16) float As[64 * HH];
    __shared__ float Ain[64 * K1];
    int tid = threadIdx.x;
    int base = blockIdx.x * 64;

    for (int i = tid; i < 64 * K1; i += 256) {
        int r = i / K1, c = i - r * K1;
        int rr = min(base + r, rows - 1);
        Ain[i] = in[rr * K1 + c];
    }
    __syncthreads();

    int lane = tid & 31, wrow = tid >> 5;
    int j0 = lane * 4, r0 = wrow * 8;

    float acc[8][4];
    init_acc(acc, *(const float4*)(b1 + j0));
#pragma unroll
    for (int k = 0; k < K1; k++) {
        float4 w = *(const float4*)(w1 + k * HH + j0);
#pragma unroll
        for (int r = 0; r < 8; r++) {
            float a = Ain[(r0 + r) * K1 + k];
            acc[r][0] += a * w.x; acc[r][1] += a * w.y;
            acc[r][2] += a * w.z; acc[r][3] += a * w.w;
        }
    }
    relu_to_smem(As, r0, j0, acc);
    __syncthreads();

    init_acc(acc, *(const float4*)(b2 + j0));
    gemm128_accum(As, w2, r0, j0, acc);

    float* out = DST ? g_e : g_x;
#pragma unroll
    for (int r = 0; r < 8; r++) {
        int rr = base + r0 + r;
        if (rr < rows)
            *(float4*)(out + rr * HH + j0) =
                make_float4(acc[r][0], acc[r][1], acc[r][2], acc[r][3]);
    }
}

// ----------------------------------------------------------------------------
// Per-node projections: g_xs = x @ W_src, g_xd = x @ W_dst (blockIdx.y selects)
// W1 points at edge_w1[l] (rows 0..127 = W_src, 128..255 = W_dst)
// ----------------------------------------------------------------------------
__global__ __launch_bounds__(256) void xsxd_kernel(const float* __restrict__ W1) {
    __shared__ __align__(16) float As[64 * HH];
    int tid = threadIdx.x;
    int base = blockIdx.x * 64;
    const float* W = W1 + blockIdx.y * (HH * HH);
    float* out = blockIdx.y ? g_xd : g_xs;

    for (int i = tid; i < 64 * 32; i += 256) {
        int r = i >> 5, c4 = i & 31;
        int nr = min(base + r, NN - 1);
        ((float4*)As)[r * 32 + c4] = ((const float4*)g_x)[nr * 32 + c4];
    }
    __syncthreads();

    int lane = tid & 31, wrow = tid >> 5;
    int j0 = lane * 4, r0 = wrow * 8;
    float acc[8][4];
    init_acc(acc, make_float4(0.f, 0.f, 0.f, 0.f));
    gemm128_accum(As, W, r0, j0, acc);

#pragma unroll
    for (int r = 0; r < 8; r++) {
        int nr = base + r0 + r;
        if (nr < NN)
            *(float4*)(out + nr * HH + j0) =
                make_float4(acc[r][0], acc[r][1], acc[r][2], acc[r][3]);
    }
}

// ----------------------------------------------------------------------------
// Fused edge layer: h = relu(xs[row] + xd[col] + e@We + b1);
//                   e_new = h@W2 + b2;  e <- e_new (in place);
//                   agg[row] += e_new (atomic scatter)
// ----------------------------------------------------------------------------
__global__ __launch_bounds__(256) void edge_layer_kernel(
    const float* __restrict__ We, const float* __restrict__ b1,
    const float* __restrict__ W2, const float* __restrict__ b2,
    const int* __restrict__ rowi, const int* __restrict__ coli) {
    __shared__ __align__(16) float As[64 * HH];
    __shared__ int rs[64], cs[64];
    int tid = threadIdx.x;
    int ebase = blockIdx.x * 64;

    for (int i = tid; i < 64 * 32; i += 256) {
        int r = i >> 5, c4 = i & 31;
        int er = min(ebase + r, EE - 1);
        ((float4*)As)[r * 32 + c4] = ((const float4*)g_e)[er * 32 + c4];
    }
    if (tid < 64) {
        int er = min(ebase + tid, EE - 1);
        rs[tid] = rowi[er];
    } else if (tid < 128) {
        int t = tid - 64;
        int er = min(ebase + t, EE - 1);
        cs[t] = coli[er];
    }
    __syncthreads();

    int lane = tid & 31, wrow = tid >> 5;
    int j0 = lane * 4, r0 = wrow * 8;
    float4 bb = *(const float4*)(b1 + j0);

    float acc[8][4];
#pragma unroll
    for (int r = 0; r < 8; r++) {
        float4 s = *(const float4*)(g_xs + rs[r0 + r] * HH + j0);
        float4 d = *(const float4*)(g_xd + cs[r0 + r] * HH + j0);
        acc[r][0] = bb.x + s.x + d.x;
        acc[r][1] = bb.y + s.y + d.y;
        acc[r][2] = bb.z + s.z + d.z;
        acc[r][3] = bb.w + s.w + d.w;
    }
    gemm128_accum(As, We, r0, j0, acc);
    __syncthreads();
    relu_to_smem(As, r0, j0, acc);
    __syncthreads();

    init_acc(acc, *(const float4*)(b2 + j0));
    gemm128_accum(As, W2, r0, j0, acc);

#pragma unroll
    for (int r = 0; r < 8; r++) {
        int er = ebase + r0 + r;
        if (er < EE) {
            float4 v = make_float4(acc[r][0], acc[r][1], acc[r][2], acc[r][3]);
            *(float4*)(g_e + er * HH + j0) = v;
            float* ap = g_agg + rs[r0 + r] * HH + j0;
            atomicAdd(ap + 0, v.x);
            atomicAdd(ap + 1, v.y);
            atomicAdd(ap + 2, v.z);
            atomicAdd(ap + 3, v.w);
        }
    }
}

// ----------------------------------------------------------------------------
// Fused node layer: x <- relu(x@Wx + agg@Wa + b1)@W2 + b2 + x
// ----------------------------------------------------------------------------
__global__ __launch_bounds__(256) void node_layer_kernel(
    const float* __restrict__ Wx, const float* __restrict__ Wa,
    const float* __restrict__ b1, const float* __restrict__ W2,
    const float* __restrict__ b2) {
    __shared__ __align__(16) float As[64 * HH];
    int tid = threadIdx.x;
    int base = blockIdx.x * 64;
    int lane = tid & 31, wrow = tid >> 5;
    int j0 = lane * 4, r0 = wrow * 8;

    for (int i = tid; i < 64 * 32; i += 256) {
        int r = i >> 5, c4 = i & 31;
        int nr = min(base + r, NN - 1);
        ((float4*)As)[r * 32 + c4] = ((const float4*)g_x)[nr * 32 + c4];
    }
    __syncthreads();

    float acc[8][4];
    init_acc(acc, *(const float4*)(b1 + j0));
    gemm128_accum(As, Wx, r0, j0, acc);
    __syncthreads();

    for (int i = tid; i < 64 * 32; i += 256) {
        int r = i >> 5, c4 = i & 31;
        int nr = min(base + r, NN - 1);
        ((float4*)As)[r * 32 + c4] = ((const float4*)g_agg)[nr * 32 + c4];
    }
    __syncthreads();
    gemm128_accum(As, Wa, r0, j0, acc);
    __syncthreads();

    relu_to_smem(As, r0, j0, acc);
    __syncthreads();

    init_acc(acc, *(const float4*)(b2 + j0));
    gemm128_accum(As, W2, r0, j0, acc);

#pragma unroll
    for (int r = 0; r < 8; r++) {
        int nr = base + r0 + r;
        if (nr < NN) {
            float4 xv = *(const float4*)(g_x + nr * HH + j0);
            *(float4*)(g_x + nr * HH + j0) =
                make_float4(acc[r][0] + xv.x, acc[r][1] + xv.y,
                            acc[r][2] + xv.z, acc[r][3] + xv.w);
        }
    }
}

// ----------------------------------------------------------------------------
// Decoder: out = relu(x@w1 + b1)@w2 + b2,  w2 is [128,3]
// ----------------------------------------------------------------------------
__global__ __launch_bounds__(256) void decoder_kernel(
    const float* __restrict__ w1, const float* __restrict__ b1,
    const float* __restrict__ w2, const float* __restrict__ b2,
    float* __restrict__ out) {
    __shared__ __align__(16) float As[64 * HH];
    int tid = threadIdx.x;
    int base = blockIdx.x * 64;
    int lane = tid & 31, wrow = tid >> 5;
    int j0 = lane * 4, r0 = wrow * 8;

    for (int i = tid; i < 64 * 32; i += 256) {
        int r = i >> 5, c4 = i & 31;
        int nr = min(base + r, NN - 1);
        ((float4*)As)[r * 32 + c4] = ((const float4*)g_x)[nr * 32 + c4];
    }
    __syncthreads();

    float acc[8][4];
    init_acc(acc, *(const float4*)(b1 + j0));
    gemm128_accum(As, w1, r0, j0, acc);
    __syncthreads();
    relu_to_smem(As, r0, j0, acc);
    __syncthreads();

    if (tid < 192) {
        int r = tid / 3, c = tid - r * 3;
        float s = b2[c];
#pragma unroll 4
        for (int k = 0; k < HH; k++) s += As[r * HH + k] * w2[k * 3 + c];
        int nr = base + r;
        if (nr < NN) out[nr * 3 + c] = s;
    }
}

// ----------------------------------------------------------------------------
extern "C" void kernel_launch(void* const* d_in, const int* in_sizes, int n_in,
                              void* d_out, int out_size) {
    const float* x_in    = (const float*)d_in[0];
    const float* eattr   = (const float*)d_in[1];
    const float* ne_w1   = (const float*)d_in[2];
    const float* ne_b1   = (const float*)d_in[3];
    const float* ne_w2   = (const float*)d_in[4];
    const float* ne_b2   = (const float*)d_in[5];
    const float* ee_w1   = (const float*)d_in[6];
    const float* ee_b1   = (const float*)d_in[7];
    const float* ee_w2   = (const float*)d_in[8];
    const float* ee_b2   = (const float*)d_in[9];
    const float* edge_w1 = (const float*)d_in[10];
    const float* edge_b1 = (const float*)d_in[11];
    const float* edge_w2 = (const float*)d_in[12];
    const float* edge_b2 = (const float*)d_in[13];
    const float* node_w1 = (const float*)d_in[14];
    const float* node_b1 = (const float*)d_in[15];
    const float* node_w2 = (const float*)d_in[16];
    const float* node_b2 = (const float*)d_in[17];
    const float* nd_w1   = (const float*)d_in[18];
    const float* nd_b1   = (const float*)d_in[19];
    const float* nd_w2   = (const float*)d_in[20];
    const float* nd_b2   = (const float*)d_in[21];
    const int*   eidx    = (const int*)d_in[22];
    const int*   rowi    = eidx;
    const int*   coli    = eidx + EE;

    const int NB_N = (NN + 63) / 64;  // 313
    const int NB_E = (EE + 63) / 64;  // 4688

    encoder_kernel<6, 0><<<NB_N, 256>>>(x_in, ne_w1, ne_b1, ne_w2, ne_b2, NN);
    encoder_kernel<3, 1><<<NB_E, 256>>>(eattr, ee_w1, ee_b1, ee_w2, ee_b2, EE);

    for (int l = 0; l < LL; l++) {
        zero_agg_kernel<<<NN * HH / 4 / 256, 256>>>();
        xsxd_kernel<<<dim3(NB_N, 2), 256>>>(edge_w1 + (size_t)l * 3 * HH * HH);
        edge_layer_kernel<<<NB_E, 256>>>(
            edge_w1 + (size_t)l * 3 * HH * HH + 2 * HH * HH,
            edge_b1 + l * HH,
            edge_w2 + (size_t)l * HH * HH,
            edge_b2 + l * HH,
            rowi, coli);
        node_layer_kernel<<<NB_N, 256>>>(
            node_w1 + (size_t)l * 2 * HH * HH,
            node_w1 + (size_t)l * 2 * HH * HH + HH * HH,
            node_b1 + l * HH,
            node_w2 + (size_t)l * HH * HH,
            node_b2 + l * HH);
    }

    decoder_kernel<<<NB_N, 256>>>(nd_w1, nd_b1, nd_w2, nd_b2, (float*)d_out);
}

// round 2
// speedup vs baseline: 1.1228x; 1.1228x over previous
#include <cuda_runtime.h>

#define NN 20000
#define EE 300000
#define HH 128
#define LL 8

typedef unsigned long long u64;

// ---------------- scratch (device globals: allocation-free contract) --------
__device__ __align__(16) float g_x  [NN * HH];
__device__ __align__(16) float g_e  [EE * HH];
__device__ __align__(16) float g_xs [NN * HH];
__device__ __align__(16) float g_xd [NN * HH];
__device__ __align__(16) float g_agg[NN * HH];

// packed (K-pair interleaved) weights: Wp[k2*256 + j*2 + s] = W[(2*k2+s)*128 + j]
__device__ __align__(16) float g_p_ne2[HH * HH];
__device__ __align__(16) float g_p_ee2[HH * HH];
__device__ __align__(16) float g_p_ew1[LL * 3 * HH * HH];
__device__ __align__(16) float g_p_ew2[LL * HH * HH];
__device__ __align__(16) float g_p_nw1[LL * 2 * HH * HH];
__device__ __align__(16) float g_p_nw2[LL * HH * HH];
__device__ __align__(16) float g_p_nd1[HH * HH];

// ---------------- f32x2 helpers ---------------------------------------------
#define FFMA2(c, a, b) \
    asm("fma.rn.f32x2 %0, %1, %2, %0;" : "+l"(c) : "l"(a), "l"(b))

__device__ __forceinline__ u64 pack2(float lo, float hi) {
    u64 r;
    asm("mov.b64 %0, {%1, %2};" : "=l"(r) : "f"(lo), "f"(hi));
    return r;
}
__device__ __forceinline__ float rsum(u64 v) {
    float lo, hi;
    asm("mov.b64 {%0, %1}, %2;" : "=f"(lo), "=f"(hi) : "l"(v));
    return lo + hi;
}

// ---------------- weight pack kernel ----------------------------------------
// dst selector: 0 ne2, 1 ee2, 2 ew1(L*3), 3 ew2(L), 4 nw1(L*2), 5 nw2(L), 6 nd1
__global__ void pack_kernel(const float* __restrict__ src, int which) {
    float* dst = which == 0 ? g_p_ne2 : which == 1 ? g_p_ee2 :
                 which == 2 ? g_p_ew1 : which == 3 ? g_p_ew2 :
                 which == 4 ? g_p_nw1 : which == 5 ? g_p_nw2 : g_p_nd1;
    int i = blockIdx.x * 256 + threadIdx.x;
    int m  = i >> 14;
    int t  = i & 16383;
    int k2 = t >> 8;
    int js = t & 255;
    int j  = js >> 1;
    int s  = js & 1;
    dst[i] = src[(m << 14) + ((2 * k2 + s) << 7) + j];
}

// ---------------- packed GEMM microkernel -----------------------------------
// acc2[r][c] = (even-K partial, odd-K partial) for row r0+r, col j0+c.
// A tile As[64][128] row-major in smem; Wp packed per above.
__device__ __forceinline__ void gemm_f2(const float* __restrict__ As,
                                        const float* __restrict__ Wp,
                                        int r0, int j0, u64 acc[8][4]) {
#pragma unroll 2
    for (int k4 = 0; k4 < 32; k4++) {
        const u64* wp0 = (const u64*)(Wp + k4 * 512 + j0 * 2);        // k2 = 2k4
        const u64* wp1 = (const u64*)(Wp + k4 * 512 + 256 + j0 * 2);  // k2 = 2k4+1
        u64 w00 = wp0[0], w01 = wp0[1], w02 = wp0[2], w03 = wp0[3];
        u64 w10 = wp1[0], w11 = wp1[1], w12 = wp1[2], w13 = wp1[3];
#pragma unroll
        for (int r = 0; r < 8; r++) {
            ulonglong2 a = *(const ulonglong2*)(As + (r0 + r) * HH + 4 * k4);
            FFMA2(acc[r][0], a.x, w00);
            FFMA2(acc[r][1], a.x, w01);
            FFMA2(acc[r][2], a.x, w02);
            FFMA2(acc[r][3], a.x, w03);
            FFMA2(acc[r][0], a.y, w10);
            FFMA2(acc[r][1], a.y, w11);
            FFMA2(acc[r][2], a.y, w12);
            FFMA2(acc[r][3], a.y, w13);
        }
    }
}

__device__ __forceinline__ void init2(u64 acc[8][4], float4 b) {
    u64 bx = pack2(b.x, 0.f), by = pack2(b.y, 0.f);
    u64 bz = pack2(b.z, 0.f), bw = pack2(b.w, 0.f);
#pragma unroll
    for (int r = 0; r < 8; r++) {
        acc[r][0] = bx; acc[r][1] = by; acc[r][2] = bz; acc[r][3] = bw;
    }
}

__device__ __forceinline__ void relu_to_smem2(float* As, int r0, int j0, u64 acc[8][4]) {
#pragma unroll
    for (int r = 0; r < 8; r++) {
        float4 h = make_float4(fmaxf(rsum(acc[r][0]), 0.f), fmaxf(rsum(acc[r][1]), 0.f),
                               fmaxf(rsum(acc[r][2]), 0.f), fmaxf(rsum(acc[r][3]), 0.f));
        *(float4*)(As + (r0 + r) * HH + j0) = h;
    }
}

// ---------------- zero the scatter accumulator ------------------------------
__global__ void zero_agg_kernel() {
    int i = blockIdx.x * blockDim.x + threadIdx.x;
    ((float4*)g_agg)[i] = make_float4(0.f, 0.f, 0.f, 0.f);
}

// ---------------- encoders ---------------------------------------------------
template <int K1, int DST>
__global__ __launch_bounds__(256, 2) void encoder_kernel(
    const float* __restrict__ in, const float* __restrict__ w1,
    const float* __restrict__ b1, const float* __restrict__ b2, int rows) {
    __shared__ __align__(16) float As[64 * HH];
    __shared__ float Ain[64 * K1];
    int tid = threadIdx.x;
    int base = blockIdx.x * 64;

    for (int i = tid; i < 64 * K1; i += 256) {
        int r = i / K1, c = i - r * K1;
        int rr = min(base + r, rows - 1);
        Ain[i] = in[rr * K1 + c];
    }
    __syncthreads();

    int lane = tid & 31, wrow = tid >> 5;
    int j0 = lane * 4, r0 = wrow * 8;

    // layer 1 (tiny K): scalar FFMA
    float a1[8][4];
    {
        float4 bb = *(const float4*)(b1 + j0);
#pragma unroll
        for (int r = 0; r < 8; r++) {
            a1[r][0] = bb.x; a1[r][1] = bb.y; a1[r][2] = bb.z; a1[r][3] = bb.w;
        }
#pragma unroll
        for (int k = 0; k < K1; k++) {
            float4 w = *(const float4*)(w1 + k * HH + j0);
#pragma unroll
            for (int r = 0; r < 8; r++) {
                float a = Ain[(r0 + r) * K1 + k];
                a1[r][0] += a * w.x; a1[r][1] += a * w.y;
                a1[r][2] += a * w.z; a1[r][3] += a * w.w;
            }
        }
#pragma unroll
        for (int r = 0; r < 8; r++) {
            float4 h = make_float4(fmaxf(a1[r][0], 0.f), fmaxf(a1[r][1], 0.f),
                                   fmaxf(a1[r][2], 0.f), fmaxf(a1[r][3], 0.f));
            *(float4*)(As + (r0 + r) * HH + j0) = h;
        }
    }
    __syncthreads();

    u64 acc[8][4];
    init2(acc, *(const float4*)(b2 + j0));
    gemm_f2(As, DST ? g_p_ee2 : g_p_ne2, r0, j0, acc);

    float* out = DST ? g_e : g_x;
#pragma unroll
    for (int r = 0; r < 8; r++) {
        int rr = base + r0 + r;
        if (rr < rows)
            *(float4*)(out + rr * HH + j0) =
                make_float4(rsum(acc[r][0]), rsum(acc[r][1]),
                            rsum(acc[r][2]), rsum(acc[r][3]));
    }
}

// ---------------- per-node projections xs = x@Wsrc, xd = x@Wdst -------------
__global__ __launch_bounds__(256, 2) void xsxd_kernel(int l) {
    __shared__ __align__(16) float As[64 * HH];
    int tid = threadIdx.x;
    int base = blockIdx.x * 64;
    const float* Wp = g_p_ew1 + (size_t)(l * 3 + blockIdx.y) * (HH * HH);
    float* out = blockIdx.y ? g_xd : g_xs;

    for (int i = tid; i < 64 * 32; i += 256) {
        int r = i >> 5, c4 = i & 31;
        int nr = min(base + r, NN - 1);
        ((float4*)As)[r * 32 + c4] = ((const float4*)g_x)[nr * 32 + c4];
    }
    __syncthreads();

    int lane = tid & 31, wrow = tid >> 5;
    int j0 = lane * 4, r0 = wrow * 8;
    u64 acc[8][4];
    init2(acc, make_float4(0.f, 0.f, 0.f, 0.f));
    gemm_f2(As, Wp, r0, j0, acc);

#pragma unroll
    for (int r = 0; r < 8; r++) {
        int nr = base + r0 + r;
        if (nr < NN)
            *(float4*)(out + nr * HH + j0) =
                make_float4(rsum(acc[r][0]), rsum(acc[r][1]),
                            rsum(acc[r][2]), rsum(acc[r][3]));
    }
}

// ---------------- fused edge layer ------------------------------------------
__global__ __launch_bounds__(256, 2) void edge_layer_kernel(
    int l, const float* __restrict__ b1, const float* __restrict__ b2,
    const int* __restrict__ rowi, const int* __restrict__ coli) {
    __shared__ __align__(16) float As[64 * HH];
    __shared__ int rs[64], cs[64];
    int tid = threadIdx.x;
    int ebase = blockIdx.x * 64;
    const float* We = g_p_ew1 + (size_t)(l * 3 + 2) * (HH * HH);
    const float* W2 = g_p_ew2 + (size_t)l * (HH * HH);

    for (int i = tid; i < 64 * 32; i += 256) {
        int r = i >> 5, c4 = i & 31;
        int er = min(ebase + r, EE - 1);
        ((float4*)As)[r * 32 + c4] = ((const float4*)g_e)[er * 32 + c4];
    }
    if (tid < 64) {
        int er = min(ebase + tid, EE - 1);
        rs[tid] = rowi[er];
    } else if (tid < 128) {
        int t = tid - 64;
        int er = min(ebase + t, EE - 1);
        cs[t] = coli[er];
    }
    __syncthreads();

    int lane = tid & 31, wrow = tid >> 5;
    int j0 = lane * 4, r0 = wrow * 8;
    float4 bb = *(const float4*)(b1 + j0);

    u64 acc[8][4];
#pragma unroll
    for (int r = 0; r < 8; r++) {
        float4 s = *(const float4*)(g_xs + (size_t)rs[r0 + r] * HH + j0);
        float4 d = *(const float4*)(g_xd + (size_t)cs[r0 + r] * HH + j0);
        acc[r][0] = pack2(bb.x + s.x + d.x, 0.f);
        acc[r][1] = pack2(bb.y + s.y + d.y, 0.f);
        acc[r][2] = pack2(bb.z + s.z + d.z, 0.f);
        acc[r][3] = pack2(bb.w + s.w + d.w, 0.f);
    }
    gemm_f2(As, We, r0, j0, acc);
    __syncthreads();
    relu_to_smem2(As, r0, j0, acc);
    __syncthreads();

    init2(acc, *(const float4*)(b2 + j0));
    gemm_f2(As, W2, r0, j0, acc);

#pragma unroll
    for (int r = 0; r < 8; r++) {
        int er = ebase + r0 + r;
        if (er < EE) {
            float4 v = make_float4(rsum(acc[r][0]), rsum(acc[r][1]),
                                   rsum(acc[r][2]), rsum(acc[r][3]));
            *(float4*)(g_e + (size_t)er * HH + j0) = v;
            float* ap = g_agg + (size_t)rs[r0 + r] * HH + j0;
            asm volatile("red.global.add.v4.f32 [%0], {%1, %2, %3, %4};"
                         :: "l"(ap), "f"(v.x), "f"(v.y), "f"(v.z), "f"(v.w)
                         : "memory");
        }
    }
}

// ---------------- fused node layer ------------------------------------------
__global__ __launch_bounds__(256, 2) void node_layer_kernel(
    int l, const float* __restrict__ b1, const float* __restrict__ b2) {
    __shared__ __align__(16) float As[64 * HH];
    int tid = threadIdx.x;
    int base = blockIdx.x * 64;
    int lane = tid & 31, wrow = tid >> 5;
    int j0 = lane * 4, r0 = wrow * 8;
    const float* Wx = g_p_nw1 + (size_t)(l * 2) * (HH * HH);
    const float* Wa = g_p_nw1 + (size_t)(l * 2 + 1) * (HH * HH);
    const float* W2 = g_p_nw2 + (size_t)l * (HH * HH);

    for (int i = tid; i < 64 * 32; i += 256) {
        int r = i >> 5, c4 = i & 31;
        int nr = min(base + r, NN - 1);
        ((float4*)As)[r * 32 + c4] = ((const float4*)g_x)[nr * 32 + c4];
    }
    __syncthreads();

    u64 acc[8][4];
    init2(acc, *(const float4*)(b1 + j0));
    gemm_f2(As, Wx, r0, j0, acc);
    __syncthreads();

    for (int i = tid; i < 64 * 32; i += 256) {
        int r = i >> 5, c4 = i & 31;
        int nr = min(base + r, NN - 1);
        ((float4*)As)[r * 32 + c4] = ((const float4*)g_agg)[nr * 32 + c4];
    }
    __syncthreads();
    gemm_f2(As, Wa, r0, j0, acc);
    __syncthreads();

    relu_to_smem2(As, r0, j0, acc);
    __syncthreads();

    init2(acc, *(const float4*)(b2 + j0));
    gemm_f2(As, W2, r0, j0, acc);

#pragma unroll
    for (int r = 0; r < 8; r++) {
        int nr = base + r0 + r;
        if (nr < NN) {
            float4 xv = *(const float4*)(g_x + (size_t)nr * HH + j0);
            *(float4*)(g_x + (size_t)nr * HH + j0) =
                make_float4(rsum(acc[r][0]) + xv.x, rsum(acc[r][1]) + xv.y,
                            rsum(acc[r][2]) + xv.z, rsum(acc[r][3]) + xv.w);
        }
    }
}

// ---------------- decoder ----------------------------------------------------
__global__ __launch_bounds__(256, 2) void decoder_kernel(
    const float* __restrict__ b1, const float* __restrict__ w2,
    const float* __restrict__ b2, float* __restrict__ out) {
    __shared__ __align__(16) float As[64 * HH];
    int tid = threadIdx.x;
    int base = blockIdx.x * 64;
    int lane = tid & 31, wrow = tid >> 5;
    int j0 = lane * 4, r0 = wrow * 8;

    for (int i = tid; i < 64 * 32; i += 256) {
        int r = i >> 5, c4 = i & 31;
        int nr = min(base + r, NN - 1);
        ((float4*)As)[r * 32 + c4] = ((const float4*)g_x)[nr * 32 + c4];
    }
    __syncthreads();

    u64 acc[8][4];
    init2(acc, *(const float4*)(b1 + j0));
    gemm_f2(As, g_p_nd1, r0, j0, acc);
    __syncthreads();
    relu_to_smem2(As, r0, j0, acc);
    __syncthreads();

    if (tid < 192) {
        int r = tid / 3, c = tid - r * 3;
        float s = b2[c];
#pragma unroll 4
        for (int k = 0; k < HH; k++) s += As[r * HH + k] * w2[k * 3 + c];
        int nr = base + r;
        if (nr < NN) out[nr * 3 + c] = s;
    }
}

// ----------------------------------------------------------------------------
extern "C" void kernel_launch(void* const* d_in, const int* in_sizes, int n_in,
                              void* d_out, int out_size) {
    const float* x_in    = (const float*)d_in[0];
    const float* eattr   = (const float*)d_in[1];
    const float* ne_w1   = (const float*)d_in[2];
    const float* ne_b1   = (const float*)d_in[3];
    const float* ne_w2   = (const float*)d_in[4];
    const float* ne_b2   = (const float*)d_in[5];
    const float* ee_w1   = (const float*)d_in[6];
    const float* ee_b1   = (const float*)d_in[7];
    const float* ee_w2   = (const float*)d_in[8];
    const float* ee_b2   = (const float*)d_in[9];
    const float* edge_w1 = (const float*)d_in[10];
    const float* edge_b1 = (const float*)d_in[11];
    const float* edge_w2 = (const float*)d_in[12];
    const float* edge_b2 = (const float*)d_in[13];
    const float* node_w1 = (const float*)d_in[14];
    const float* node_b1 = (const float*)d_in[15];
    const float* node_w2 = (const float*)d_in[16];
    const float* node_b2 = (const float*)d_in[17];
    const float* nd_w1   = (const float*)d_in[18];
    const float* nd_b1   = (const float*)d_in[19];
    const float* nd_w2   = (const float*)d_in[20];
    const float* nd_b2   = (const float*)d_in[21];
    const int*   eidx    = (const int*)d_in[22];
    const int*   rowi    = eidx;
    const int*   coli    = eidx + EE;

    const int NB_N = (NN + 63) / 64;  // 313
    const int NB_E = (EE + 63) / 64;  // 4688

    // pack all 128x128 weight matrices into K-pair-interleaved layout
    pack_kernel<<<64, 256>>>(ne_w2, 0);
    pack_kernel<<<64, 256>>>(ee_w2, 1);
    pack_kernel<<<LL * 3 * 64, 256>>>(edge_w1, 2);
    pack_kernel<<<LL * 64, 256>>>(edge_w2, 3);
    pack_kernel<<<LL * 2 * 64, 256>>>(node_w1, 4);
    pack_kernel<<<LL * 64, 256>>>(node_w2, 5);
    pack_kernel<<<64, 256>>>(nd_w1, 6);

    encoder_kernel<6, 0><<<NB_N, 256>>>(x_in, ne_w1, ne_b1, ne_b2, NN);
    encoder_kernel<3, 1><<<NB_E, 256>>>(eattr, ee_w1, ee_b1, ee_b2, EE);

    for (int l = 0; l < LL; l++) {
        zero_agg_kernel<<<NN * HH / 4 / 256, 256>>>();
        xsxd_kernel<<<dim3(NB_N, 2), 256>>>(l);
        edge_layer_kernel<<<NB_E, 256>>>(l, edge_b1 + l * HH, edge_b2 + l * HH,
                                         rowi, coli);
        node_layer_kernel<<<NB_N, 256>>>(l, node_b1 + l * HH, node_b2 + l * HH);
    }

    decoder_kernel<<<NB_N, 256>>>(nd_b1, nd_w2, nd_b2, (float*)d_out);
}

// round 4
// speedup vs baseline: 1.6506x; 1.4701x over previous
#include <cuda_runtime.h>
#include <cuda_bf16.h>
#include <cstdint>

#define NN 20000
#define EE 300000
#define HH 128
#define LL 8
#define PITCH 272   // smem row pitch in bytes (136 bf16) — conflict-free for ldmatrix

// smem region offsets (bytes)
#define A_HI 0
#define A_LO 34816
#define B_HI 69632
#define B_LO 104448
#define SM_AB 139264
#define E_SMEM (SM_AB + 1024)

// ============================ scratch globals ===============================
__device__ __align__(16) float g_x  [NN * HH];
__device__ __align__(16) float g_e  [EE * HH];
__device__ __align__(16) float g_xs [NN * HH];
__device__ __align__(16) float g_xd [NN * HH];
__device__ __align__(16) float g_agg[NN * HH];

// packed weights: per matrix [hi 128x128 | lo 128x128] bf16, TRANSPOSED
// (row n = output col j, col k), row-major — ldmatrix-ready.
__device__ __align__(16) __nv_bfloat16 g_wsrc[LL * 32768];
__device__ __align__(16) __nv_bfloat16 g_wdst[LL * 32768];
__device__ __align__(16) __nv_bfloat16 g_we  [LL * 32768];
__device__ __align__(16) __nv_bfloat16 g_we2 [LL * 32768];
__device__ __align__(16) __nv_bfloat16 g_wnx [LL * 32768];
__device__ __align__(16) __nv_bfloat16 g_wna [LL * 32768];
__device__ __align__(16) __nv_bfloat16 g_wn2 [LL * 32768];
__device__ __align__(16) __nv_bfloat16 g_wne2[32768];
__device__ __align__(16) __nv_bfloat16 g_wee2[32768];

// ============================ helpers =======================================
__device__ __forceinline__ uint32_t smem_u32(const void* p) {
    uint32_t a;
    asm("{ .reg .u64 t; cvta.to.shared.u64 t, %1; cvt.u32.u64 %0, t; }"
        : "=r"(a) : "l"(p));
    return a;
}

__device__ __forceinline__ void ldsm4(uint32_t addr, uint32_t r[4]) {
    asm volatile("ldmatrix.sync.aligned.m8n8.x4.shared.b16 {%0,%1,%2,%3}, [%4];"
                 : "=r"(r[0]), "=r"(r[1]), "=r"(r[2]), "=r"(r[3]) : "r"(addr));
}

__device__ __forceinline__ void mma16816(float c[4], const uint32_t a[4],
                                         const uint32_t* b) {
    asm volatile("mma.sync.aligned.m16n8k16.row.col.f32.bf16.bf16.f32 "
                 "{%0,%1,%2,%3}, {%4,%5,%6,%7}, {%8,%9}, {%0,%1,%2,%3};"
                 : "+f"(c[0]), "+f"(c[1]), "+f"(c[2]), "+f"(c[3])
                 : "r"(a[0]), "r"(a[1]), "r"(a[2]), "r"(a[3]),
                   "r"(b[0]), "r"(b[1]));
}

__device__ __forceinline__ void split2(float a, float b, uint32_t& hi, uint32_t& lo) {
    __nv_bfloat16 ah = __float2bfloat16_rn(a), bh = __float2bfloat16_rn(b);
    float ar = a - __bfloat162float(ah), br = b - __bfloat162float(bh);
    hi = (uint32_t)__bfloat16_as_ushort(ah) |
         ((uint32_t)__bfloat16_as_ushort(bh) << 16);
    lo = (uint32_t)__bfloat16_as_ushort(__float2bfloat16_rn(ar)) |
         ((uint32_t)__bfloat16_as_ushort(__float2bfloat16_rn(br)) << 16);
}

// 3-term emulated fp32 GEMM: acc += A[128x128] @ Wt[128x128]^T for this warp's
// 32x64 tile.  wr in 0..3 (row tile), wc in 0..1 (col tile).
__device__ __forceinline__ void warp_gemm3(const char* sm, int wr, int wc,
                                           int lid, float acc[2][8][4]) {
    uint32_t sb = smem_u32(sm);
    uint32_t a_base = sb + A_HI + (uint32_t)(wr * 32 + (lid & 15)) * PITCH +
                      (uint32_t)((lid >> 4) * 8) * 2;
    uint32_t b_base = sb + B_HI +
        (uint32_t)(wc * 64 + ((lid >> 4) & 1) * 8 + (lid & 7)) * PITCH +
        (uint32_t)(((lid >> 3) & 1) * 8) * 2;
#pragma unroll
    for (int ks = 0; ks < 8; ks++) {
        uint32_t ko = ks * 32;
        uint32_t Ah[2][4], Al[2][4], Bh[4][4], Bl[4][4];
        ldsm4(a_base + ko, Ah[0]);
        ldsm4(a_base + 16 * PITCH + ko, Ah[1]);
        ldsm4(a_base + (A_LO - A_HI) + ko, Al[0]);
        ldsm4(a_base + (A_LO - A_HI) + 16 * PITCH + ko, Al[1]);
#pragma unroll
        for (int g = 0; g < 4; g++) {
            ldsm4(b_base + g * 16 * PITCH + ko, Bh[g]);
            ldsm4(b_base + (B_LO - B_HI) + g * 16 * PITCH + ko, Bl[g]);
        }
#pragma unroll
        for (int m = 0; m < 2; m++)
#pragma unroll
            for (int g = 0; g < 4; g++)
#pragma unroll
                for (int s = 0; s < 2; s++) {
                    float* c = acc[m][g * 2 + s];
                    mma16816(c, Ah[m], &Bh[g][2 * s]);
                    mma16816(c, Al[m], &Bh[g][2 * s]);
                    mma16816(c, Ah[m], &Bl[g][2 * s]);
                }
    }
}

#define ZACC(acc)                                   \
    _Pragma("unroll") for (int _m = 0; _m < 2; _m++) \
    _Pragma("unroll") for (int _n = 0; _n < 8; _n++) \
    _Pragma("unroll") for (int _q = 0; _q < 4; _q++) acc[_m][_n][_q] = 0.f;

// load a [128,128] f32 tile (row-clamped) -> bf16 hi/lo into A smem region
__device__ __forceinline__ void load_split_tile(const float* __restrict__ src,
                                                int base, int maxr, char* sm) {
    for (int g = threadIdx.x; g < 2048; g += 256) {
        int r = g >> 4, c8 = (g & 15) << 3;
        int rr = min(base + r, maxr - 1);
        const float* p = src + (size_t)rr * HH + c8;
        float4 v0 = *(const float4*)p;
        float4 v1 = *(const float4*)(p + 4);
        uint32_t h0, l0, h1, l1, h2, l2, h3, l3;
        split2(v0.x, v0.y, h0, l0); split2(v0.z, v0.w, h1, l1);
        split2(v1.x, v1.y, h2, l2); split2(v1.z, v1.w, h3, l3);
        char* dst = sm + (size_t)r * PITCH + c8 * 2;
        *(uint4*)(dst + A_HI) = make_uint4(h0, h1, h2, h3);
        *(uint4*)(dst + A_LO) = make_uint4(l0, l1, l2, l3);
    }
}

// copy a packed weight matrix (hi 32KB + lo 32KB) into B smem region
__device__ __forceinline__ void copy_w(const __nv_bfloat16* __restrict__ w,
                                       char* sm) {
    const uint4* s = (const uint4*)w;
    for (int i = threadIdx.x; i < 2048; i += 256) {
        int r = i >> 4, c = i & 15;
        char* dst = sm + (size_t)r * PITCH + c * 16;
        *(uint4*)(dst + B_HI) = s[i];
        *(uint4*)(dst + B_LO) = s[i + 2048];
    }
}

// ============================ pack kernel ===================================
__global__ void pack_w(const float* __restrict__ src, int which, int stride) {
    __nv_bfloat16* dst =
        which == 0 ? g_wsrc : which == 1 ? g_wdst : which == 2 ? g_we :
        which == 3 ? g_we2  : which == 4 ? g_wnx  : which == 5 ? g_wna :
        which == 6 ? g_wn2  : which == 7 ? g_wne2 : g_wee2;
    int i = blockIdx.x * 256 + threadIdx.x;
    int m = i >> 14, t = i & 16383;
    int n = t >> 7, k = t & 127;
    float v = src[(size_t)m * stride + k * HH + n];   // transpose
    __nv_bfloat16 h = __float2bfloat16_rn(v);
    __nv_bfloat16 lo = __float2bfloat16_rn(v - __bfloat162float(h));
    __nv_bfloat16* b = dst + (size_t)m * 32768;
    b[t] = h;
    b[t + 16384] = lo;
}

__global__ void zero_agg_kernel() {
    int i = blockIdx.x * blockDim.x + threadIdx.x;
    ((float4*)g_agg)[i] = make_float4(0.f, 0.f, 0.f, 0.f);
}

// =========================== edge layer =====================================
__global__ __launch_bounds__(256) void edge_layer_mma(
    int l, const float* __restrict__ b1, const float* __restrict__ b2,
    const int* __restrict__ rowi, const int* __restrict__ coli) {
    extern __shared__ __align__(16) char sm[];
    int tid = threadIdx.x, lid = tid & 31, wid = tid >> 5;
    int wr = wid >> 1, wc = wid & 1;
    int ebase = blockIdx.x * 128;
    int* rs = (int*)(sm + SM_AB);
    int* cs = rs + 128;

    load_split_tile(g_e, ebase, EE, sm);
    copy_w(g_we + (size_t)l * 32768, sm);
    if (tid < 128) {
        int er = min(ebase + tid, EE - 1);
        rs[tid] = rowi[er];
        cs[tid] = coli[er];
    }
    __syncthreads();

    float acc[2][8][4];
    ZACC(acc);
    warp_gemm3(sm, wr, wc, lid, acc);
    __syncthreads();

    int lq = lid >> 2, lr = (lid & 3) * 2;
#pragma unroll
    for (int m = 0; m < 2; m++) {
        int rA = wr * 32 + m * 16 + lq, rB = rA + 8;
        const float* xsA = g_xs + (size_t)rs[rA] * HH;
        const float* xdA = g_xd + (size_t)cs[rA] * HH;
        const float* xsB = g_xs + (size_t)rs[rB] * HH;
        const float* xdB = g_xd + (size_t)cs[rB] * HH;
#pragma unroll
        for (int n = 0; n < 8; n++) {
            int col = wc * 64 + n * 8 + lr;
            float2 bv = *(const float2*)(b1 + col);
            float2 sA = *(const float2*)(xsA + col);
            float2 dA = *(const float2*)(xdA + col);
            float2 sB = *(const float2*)(xsB + col);
            float2 dB = *(const float2*)(xdB + col);
            float* c = acc[m][n];
            float h0 = fmaxf(c[0] + bv.x + sA.x + dA.x, 0.f);
            float h1 = fmaxf(c[1] + bv.y + sA.y + dA.y, 0.f);
            float h2 = fmaxf(c[2] + bv.x + sB.x + dB.x, 0.f);
            float h3 = fmaxf(c[3] + bv.y + sB.y + dB.y, 0.f);
            uint32_t hi, lo;
            split2(h0, h1, hi, lo);
            *(uint32_t*)(sm + A_HI + (size_t)rA * PITCH + col * 2) = hi;
            *(uint32_t*)(sm + A_LO + (size_t)rA * PITCH + col * 2) = lo;
            split2(h2, h3, hi, lo);
            *(uint32_t*)(sm + A_HI + (size_t)rB * PITCH + col * 2) = hi;
            *(uint32_t*)(sm + A_LO + (size_t)rB * PITCH + col * 2) = lo;
        }
    }
    copy_w(g_we2 + (size_t)l * 32768, sm);
    __syncthreads();

    ZACC(acc);
    warp_gemm3(sm, wr, wc, lid, acc);

#pragma unroll
    for (int m = 0; m < 2; m++) {
        int rA = wr * 32 + m * 16 + lq, rB = rA + 8;
        int eA = ebase + rA, eB = ebase + rB;
        float* aggA = g_agg + (size_t)rs[rA] * HH;
        float* aggB = g_agg + (size_t)rs[rB] * HH;
#pragma unroll
        for (int n = 0; n < 8; n++) {
            int col = wc * 64 + n * 8 + lr;
            float2 bv = *(const float2*)(b2 + col);
            float* c = acc[m][n];
            if (eA < EE) {
                float vx = c[0] + bv.x, vy = c[1] + bv.y;
                *(float2*)(g_e + (size_t)eA * HH + col) = make_float2(vx, vy);
                asm volatile("red.global.add.v2.f32 [%0], {%1, %2};"
                             :: "l"(aggA + col), "f"(vx), "f"(vy) : "memory");
            }
            if (eB < EE) {
                float vx = c[2] + bv.x, vy = c[3] + bv.y;
                *(float2*)(g_e + (size_t)eB * HH + col) = make_float2(vx, vy);
                asm volatile("red.global.add.v2.f32 [%0], {%1, %2};"
                             :: "l"(aggB + col), "f"(vx), "f"(vy) : "memory");
            }
        }
    }
}

// ======================= xs/xd projections ==================================
__global__ __launch_bounds__(256) void xsxd_mma(int l) {
    extern __shared__ __align__(16) char sm[];
    int tid = threadIdx.x, lid = tid & 31, wid = tid >> 5;
    int wr = wid >> 1, wc = wid & 1;
    int base = blockIdx.x * 128;

    load_split_tile(g_x, base, NN, sm);
    copy_w(g_wsrc + (size_t)l * 32768, sm);
    __syncthreads();

    float acc[2][8][4];
    ZACC(acc);
    warp_gemm3(sm, wr, wc, lid, acc);

    int lq = lid >> 2, lr = (lid & 3) * 2;
#pragma unroll
    for (int m = 0; m < 2; m++) {
        int rA = wr * 32 + m * 16 + lq, rB = rA + 8;
#pragma unroll
        for (int n = 0; n < 8; n++) {
            int col = wc * 64 + n * 8 + lr;
            float* c = acc[m][n];
            if (base + rA < NN)
                *(float2*)(g_xs + (size_t)(base + rA) * HH + col) =
                    make_float2(c[0], c[1]);
            if (base + rB < NN)
                *(float2*)(g_xs + (size_t)(base + rB) * HH + col) =
                    make_float2(c[2], c[3]);
        }
    }
    __syncthreads();
    copy_w(g_wdst + (size_t)l * 32768, sm);
    __syncthreads();

    ZACC(acc);
    warp_gemm3(sm, wr, wc, lid, acc);
#pragma unroll
    for (int m = 0; m < 2; m++) {
        int rA = wr * 32 + m * 16 + lq, rB = rA + 8;
#pragma unroll
        for (int n = 0; n < 8; n++) {
            int col = wc * 64 + n * 8 + lr;
            float* c = acc[m][n];
            if (base + rA < NN)
                *(float2*)(g_xd + (size_t)(base + rA) * HH + col) =
                    make_float2(c[0], c[1]);
            if (base + rB < NN)
                *(float2*)(g_xd + (size_t)(base + rB) * HH + col) =
                    make_float2(c[2], c[3]);
        }
    }
}

// =========================== node layer =====================================
__global__ __launch_bounds__(256) void node_layer_mma(
    int l, const float* __restrict__ b1, const float* __restrict__ b2) {
    extern __shared__ __align__(16) char sm[];
    int tid = threadIdx.x, lid = tid & 31, wid = tid >> 5;
    int wr = wid >> 1, wc = wid & 1;
    int base = blockIdx.x * 128;

    load_split_tile(g_x, base, NN, sm);
    copy_w(g_wnx + (size_t)l * 32768, sm);
    __syncthreads();

    float acc[2][8][4];
    ZACC(acc);
    warp_gemm3(sm, wr, wc, lid, acc);
    __syncthreads();

    load_split_tile(g_agg, base, NN, sm);
    copy_w(g_wna + (size_t)l * 32768, sm);
    __syncthreads();
    warp_gemm3(sm, wr, wc, lid, acc);   // accumulate second term
    __syncthreads();

    int lq = lid >> 2, lr = (lid & 3) * 2;
#pragma unroll
    for (int m = 0; m < 2; m++) {
        int rA = wr * 32 + m * 16 + lq, rB = rA + 8;
#pragma unroll
        for (int n = 0; n < 8; n++) {
            int col = wc * 64 + n * 8 + lr;
            float2 bv = *(const float2*)(b1 + col);
            float* c = acc[m][n];
            float h0 = fmaxf(c[0] + bv.x, 0.f);
            float h1 = fmaxf(c[1] + bv.y, 0.f);
            float h2 = fmaxf(c[2] + bv.x, 0.f);
            float h3 = fmaxf(c[3] + bv.y, 0.f);
            uint32_t hi, lo;
            split2(h0, h1, hi, lo);
            *(uint32_t*)(sm + A_HI + (size_t)rA * PITCH + col * 2) = hi;
            *(uint32_t*)(sm + A_LO + (size_t)rA * PITCH + col * 2) = lo;
            split2(h2, h3, hi, lo);
            *(uint32_t*)(sm + A_HI + (size_t)rB * PITCH + col * 2) = hi;
            *(uint32_t*)(sm + A_LO + (size_t)rB * PITCH + col * 2) = lo;
        }
    }
    copy_w(g_wn2 + (size_t)l * 32768, sm);
    __syncthreads();

    ZACC(acc);
    warp_gemm3(sm, wr, wc, lid, acc);

#pragma unroll
    for (int m = 0; m < 2; m++) {
        int rA = wr * 32 + m * 16 + lq, rB = rA + 8;
#pragma unroll
        for (int n = 0; n < 8; n++) {
            int col = wc * 64 + n * 8 + lr;
            float2 bv = *(const float2*)(b2 + col);
            float* c = acc[m][n];
            if (base + rA < NN) {
                float* xp = g_x + (size_t)(base + rA) * HH + col;
                float2 xv = *(float2*)xp;
                *(float2*)xp = make_float2(c[0] + bv.x + xv.x, c[1] + bv.y + xv.y);
            }
            if (base + rB < NN) {
                float* xp = g_x + (size_t)(base + rB) * HH + col;
                float2 xv = *(float2*)xp;
                *(float2*)xp = make_float2(c[2] + bv.x + xv.x, c[3] + bv.y + xv.y);
            }
        }
    }
}

// ============================ encoders ======================================
template <int K1, int DST>
__global__ __launch_bounds__(256) void encoder_mma(
    const float* __restrict__ in, const float* __restrict__ w1,
    const float* __restrict__ b1, const float* __restrict__ b2, int rows) {
    extern __shared__ __align__(16) char sm[];
    int tid = threadIdx.x, lid = tid & 31, wid = tid >> 5;
    int wr = wid >> 1, wc = wid & 1;
    int base = blockIdx.x * 128;

    for (int g = tid; g < 2048; g += 256) {
        int r = g >> 4, c8 = (g & 15) << 3;
        int rr = min(base + r, rows - 1);
        float vin[K1];
#pragma unroll
        for (int k = 0; k < K1; k++) vin[k] = in[(size_t)rr * K1 + k];
        float h[8];
#pragma unroll
        for (int c = 0; c < 8; c++) {
            int cc = c8 + c;
            float s = b1[cc];
#pragma unroll
            for (int k = 0; k < K1; k++) s += vin[k] * w1[k * HH + cc];
            h[c] = fmaxf(s, 0.f);
        }
        uint32_t hv[4], lv[4];
        split2(h[0], h[1], hv[0], lv[0]);
        split2(h[2], h[3], hv[1], lv[1]);
        split2(h[4], h[5], hv[2], lv[2]);
        split2(h[6], h[7], hv[3], lv[3]);
        char* dst = sm + (size_t)r * PITCH + c8 * 2;
        *(uint4*)(dst + A_HI) = make_uint4(hv[0], hv[1], hv[2], hv[3]);
        *(uint4*)(dst + A_LO) = make_uint4(lv[0], lv[1], lv[2], lv[3]);
    }
    copy_w(DST ? g_wee2 : g_wne2, sm);
    __syncthreads();

    float acc[2][8][4];
    ZACC(acc);
    warp_gemm3(sm, wr, wc, lid, acc);

    float* out = DST ? g_e : g_x;
    int lq = lid >> 2, lr = (lid & 3) * 2;
#pragma unroll
    for (int m = 0; m < 2; m++) {
        int rA = wr * 32 + m * 16 + lq, rB = rA + 8;
#pragma unroll
        for (int n = 0; n < 8; n++) {
            int col = wc * 64 + n * 8 + lr;
            float2 bv = *(const float2*)(b2 + col);
            float* c = acc[m][n];
            if (base + rA < rows)
                *(float2*)(out + (size_t)(base + rA) * HH + col) =
                    make_float2(c[0] + bv.x, c[1] + bv.y);
            if (base + rB < rows)
                *(float2*)(out + (size_t)(base + rB) * HH + col) =
                    make_float2(c[2] + bv.x, c[3] + bv.y);
        }
    }
}

// ============================ decoder (scalar) ==============================
__global__ __launch_bounds__(256) void decoder_kernel(
    const float* __restrict__ w1, const float* __restrict__ b1,
    const float* __restrict__ w2, const float* __restrict__ b2,
    float* __restrict__ out) {
    __shared__ __align__(16) float As[64 * HH];
    int tid = threadIdx.x;
    int base = blockIdx.x * 64;
    int lane = tid & 31, wrow = tid >> 5;
    int j0 = lane * 4, r0 = wrow * 8;

    for (int i = tid; i < 64 * 32; i += 256) {
        int r = i >> 5, c4 = i & 31;
        int nr = min(base + r, NN - 1);
        ((float4*)As)[r * 32 + c4] = ((const float4*)g_x)[(size_t)nr * 32 + c4];
    }
    __syncthreads();

    float acc[8][4];
    float4 bb = *(const float4*)(b1 + j0);
#pragma unroll
    for (int r = 0; r < 8; r++) {
        acc[r][0] = bb.x; acc[r][1] = bb.y; acc[r][2] = bb.z; acc[r][3] = bb.w;
    }
#pragma unroll 2
    for (int k4 = 0; k4 < 32; k4++) {
        const float* wr = w1 + (k4 * 4) * HH + j0;
        float4 w0 = *(const float4*)(wr);
        float4 w1v = *(const float4*)(wr + HH);
        float4 w2v = *(const float4*)(wr + 2 * HH);
        float4 w3v = *(const float4*)(wr + 3 * HH);
#pragma unroll
        for (int r = 0; r < 8; r++) {
            float4 a = *(const float4*)(As + (r0 + r) * HH + k4 * 4);
            acc[r][0] += a.x * w0.x + a.y * w1v.x + a.z * w2v.x + a.w * w3v.x;
            acc[r][1] += a.x * w0.y + a.y * w1v.y + a.z * w2v.y + a.w * w3v.y;
            acc[r][2] += a.x * w0.z + a.y * w1v.z + a.z * w2v.z + a.w * w3v.z;
            acc[r][3] += a.x * w0.w + a.y * w1v.w + a.z * w2v.w + a.w * w3v.w;
        }
    }
    __syncthreads();
#pragma unroll
    for (int r = 0; r < 8; r++) {
        float4 h = make_float4(fmaxf(acc[r][0], 0.f), fmaxf(acc[r][1], 0.f),
                               fmaxf(acc[r][2], 0.f), fmaxf(acc[r][3], 0.f));
        *(float4*)(As + (r0 + r) * HH + j0) = h;
    }
    __syncthreads();

    if (tid < 192) {
        int r = tid / 3, c = tid - r * 3;
        float s = b2[c];
#pragma unroll 4
        for (int k = 0; k < HH; k++) s += As[r * HH + k] * w2[k * 3 + c];
        int nr = base + r;
        if (nr < NN) out[nr * 3 + c] = s;
    }
}

// ============================================================================
extern "C" void kernel_launch(void* const* d_in, const int* in_sizes, int n_in,
                              void* d_out, int out_size) {
    const float* x_in    = (const float*)d_in[0];
    const float* eattr   = (const float*)d_in[1];
    const float* ne_w1   = (const float*)d_in[2];
    const float* ne_b1   = (const float*)d_in[3];
    const float* ne_w2   = (const float*)d_in[4];
    const float* ne_b2   = (const float*)d_in[5];
    const float* ee_w1   = (const float*)d_in[6];
    const float* ee_b1   = (const float*)d_in[7];
    const float* ee_w2   = (const float*)d_in[8];
    const float* ee_b2   = (const float*)d_in[9];
    const float* edge_w1 = (const float*)d_in[10];
    const float* edge_b1 = (const float*)d_in[11];
    const float* edge_w2 = (const float*)d_in[12];
    const float* edge_b2 = (const float*)d_in[13];
    const float* node_w1 = (const float*)d_in[14];
    const float* node_b1 = (const float*)d_in[15];
    const float* node_w2 = (const float*)d_in[16];
    const float* node_b2 = (const float*)d_in[17];
    const float* nd_w1   = (const float*)d_in[18];
    const float* nd_b1   = (const float*)d_in[19];
    const float* nd_w2   = (const float*)d_in[20];
    const float* nd_b2   = (const float*)d_in[21];
    const int*   eidx    = (const int*)d_in[22];
    const int*   rowi    = eidx;
    const int*   coli    = eidx + EE;

    cudaFuncSetAttribute(edge_layer_mma,
                         cudaFuncAttributeMaxDynamicSharedMemorySize, E_SMEM);
    cudaFuncSetAttribute(xsxd_mma,
                         cudaFuncAttributeMaxDynamicSharedMemorySize, SM_AB);
    cudaFuncSetAttribute(node_layer_mma,
                         cudaFuncAttributeMaxDynamicSharedMemorySize, SM_AB);
    cudaFuncSetAttribute(encoder_mma<6, 0>,
                         cudaFuncAttributeMaxDynamicSharedMemorySize, SM_AB);
    cudaFuncSetAttribute(encoder_mma<3, 1>,
                         cudaFuncAttributeMaxDynamicSharedMemorySize, SM_AB);

    // pack weights: transpose + bf16 hi/lo split
    pack_w<<<LL * 64, 256>>>(edge_w1,             0, 3 * 16384);
    pack_w<<<LL * 64, 256>>>(edge_w1 + 16384,     1, 3 * 16384);
    pack_w<<<LL * 64, 256>>>(edge_w1 + 2 * 16384, 2, 3 * 16384);
    pack_w<<<LL * 64, 256>>>(edge_w2,             3, 16384);
    pack_w<<<LL * 64, 256>>>(node_w1,             4, 2 * 16384);
    pack_w<<<LL * 64, 256>>>(node_w1 + 16384,     5, 2 * 16384);
    pack_w<<<LL * 64, 256>>>(node_w2,             6, 16384);
    pack_w<<<64, 256>>>(ne_w2, 7, 16384);
    pack_w<<<64, 256>>>(ee_w2, 8, 16384);

    const int TB_N = (NN + 127) / 128;   // 157
    const int TB_E = (EE + 127) / 128;   // 2344

    encoder_mma<6, 0><<<TB_N, 256, SM_AB>>>(x_in, ne_w1, ne_b1, ne_b2, NN);
    encoder_mma<3, 1><<<TB_E, 256, SM_AB>>>(eattr, ee_w1, ee_b1, ee_b2, EE);

    for (int l = 0; l < LL; l++) {
        zero_agg_kernel<<<NN * HH / 4 / 256, 256>>>();
        xsxd_mma<<<TB_N, 256, SM_AB>>>(l);
        edge_layer_mma<<<TB_E, 256, E_SMEM>>>(l, edge_b1 + l * HH,
                                              edge_b2 + l * HH, rowi, coli);
        node_layer_mma<<<TB_N, 256, SM_AB>>>(l, node_b1 + l * HH,
                                             node_b2 + l * HH);
    }

    decoder_kernel<<<(NN + 63) / 64, 256>>>(nd_w1, nd_b1, nd_w2, nd_b2,
                                            (float*)d_out);
}